// round 15
// baseline (speedup 1.0000x reference)
#include <cuda_runtime.h>
#include <cuda_fp16.h>
#include <math.h>
#include <stdint.h>

#define Bn   8
#define Tn   128
#define U1n  33
#define Dn   512
#define Vn   4096
#define BTU  (Tn*U1n)          // 4224
#define ROWS (Bn*BTU)          // 33792
#define MTL  (ROWS/128)        // 264 M-tiles (33 per batch)
#define NVT  (Vn/128)          // 32 vocab tiles
#define NCTA 148
#define L2E  1.442695040888963f
#define LN2  0.6931471805599453f
#define U1P  34                // padded lattice stride (bank-conflict-free)
#define BTUP (Tn*U1P)          // 4352

// smem layout (bytes) for maingemm
#define SM_A     0u            // 128 x 512 fp16 = 131072
#define SM_B     131072u       // 3 stages x 16384 (128n x 64k fp16)
#define SM_BIAS  180224u       // 4096 floats = 16384
#define SM_RED   196608u       // 2 x 512 floats = 4096
#define SM_TOT   200704u

// ---------------- device scratch ----------------
__device__ __align__(16) __half g_Wh[(size_t)Vn*Dn];
__device__ float g_pE0[ROWS];   // start segments (vt0 == 0)
__device__ float g_pE1[ROWS];   // end segments (vt0 > 0, reaches vtile 31)
__device__ float g_pE2[ROWS];   // middle segments (rare 3-way splits)
__device__ float g_pR0[ROWS];
__device__ float g_pR1[ROWS];
__device__ float g_pR2[ROWS];
__device__ float g_blank[ROWS];
__device__ float g_tgt[ROWS];
__device__ float g_part[Bn];
__device__ unsigned g_done;
__device__ int g_mtlist[MTL];          // useful mtile ids
__device__ int g_ustart[NCTA + 1];     // per-CTA unit ranges

// ---------------- helpers ----------------
__device__ __forceinline__ uint32_t smem_u32(const void* p) {
    uint32_t a;
    asm("{ .reg .u64 t; cvta.to.shared.u64 t, %1; cvt.u32.u64 %0, t; }" : "=r"(a) : "l"(p));
    return a;
}
__device__ __forceinline__ void cpa16(uint32_t dst, const void* src) {
    asm volatile("cp.async.cg.shared.global [%0], [%1], 16;" :: "r"(dst), "l"(src));
}
__device__ __forceinline__ float ex2a(float x) {
    float y; asm("ex2.approx.ftz.f32 %0, %1;" : "=f"(y) : "f"(x)); return y;
}
__device__ __forceinline__ float lg2a(float x) {
    float y; asm("lg2.approx.ftz.f32 %0, %1;" : "=f"(y) : "f"(x)); return y;
}
// log2-domain logaddexp: max + lg2(1 + 2^(min-max)). MUFU-only, short chain.
__device__ __forceinline__ float laddexp2(float a, float b) {
    float m = fmaxf(a, b);
    float d = fminf(a, b) - m;
    return m + lg2a(1.0f + ex2a(d));
}
// fast 2^z, FFMA-only (no MUFU). |rel err| ~2e-6.
__device__ __forceinline__ float exp2_fast(float z) {
    float zc = z + 12582912.f;
    int   ni = __float_as_int(zc);
    float n  = zc - 12582912.f;
    float f  = z - n;
    float p  = fmaf(0.0013333558f, f, 0.0096181291f);
    p = fmaf(p, f, 0.0555041087f);
    p = fmaf(p, f, 0.2402265069f);
    p = fmaf(p, f, 0.6931471806f);
    p = fmaf(p, f, 1.0f);
    return __int_as_float(__float_as_int(p) + (ni << 23));
}

// ---------------------------------------------------------------------------
// Kernel 0: convert W fp32 -> fp16 (blocks 0..1023) + schedule (block 1024)
// ---------------------------------------------------------------------------
__global__ void __launch_bounds__(256) convW_kernel(const float* __restrict__ w,
                                                    const int* __restrict__ src)
{
    if (blockIdx.x == 1024) {
        // deterministic schedule: useful-mtile list + per-CTA unit partition
        if (threadIdx.x != 0) return;
        int S[Bn];
#pragma unroll
        for (int b = 0; b < Bn; b++) S[b] = src[b];
        int n = 0;
        for (int mt = 0; mt < MTL; mt++) {
            int b = mt / 33, m = mt % 33;
            if ((m * 128) / 33 < S[b]) g_mtlist[n++] = mt;
        }
        int utot = n * NVT;
        int ub = utot / NCTA, ur = utot % NCTA;
        int acc = 0;
        for (int c = 0; c <= NCTA; c++) {
            g_ustart[c] = acc;
            acc += ub + (c < ur ? 1 : 0);
        }
        return;
    }
    int i = blockIdx.x * 256 + threadIdx.x;          // each handles 8 floats
    const float4* srcp = reinterpret_cast<const float4*>(w) + (size_t)i * 2;
    float4 v0 = srcp[0], v1 = srcp[1];
    __half2 p0 = __floats2half2_rn(v0.x, v0.y);
    __half2 p1 = __floats2half2_rn(v0.z, v0.w);
    __half2 p2 = __floats2half2_rn(v1.x, v1.y);
    __half2 p3 = __floats2half2_rn(v1.z, v1.w);
    uint4 o;
    o.x = *reinterpret_cast<uint32_t*>(&p0);
    o.y = *reinterpret_cast<uint32_t*>(&p1);
    o.z = *reinterpret_cast<uint32_t*>(&p2);
    o.w = *reinterpret_cast<uint32_t*>(&p3);
    *reinterpret_cast<uint4*>(g_Wh + (size_t)i * 8) = o;
}

// ---------------------------------------------------------------------------
// Kernel 1: persistent fp16 mma.sync GEMM + deferred (overlapped) epilogue
//   148 CTAs x 256 threads; length-aware unit partition over (mtile, vtile)
// ---------------------------------------------------------------------------
extern __shared__ char dynsm[];

__device__ __forceinline__ void load_Bchunk(uint32_t Bs, int cg, int stage, int tid)
{
    const __half* wsrc = g_Wh + ((size_t)(cg >> 3)) * 128 * Dn + (cg & 7) * 64;
    const uint32_t dstb = Bs + (uint32_t)stage * 16384u;
#pragma unroll
    for (int it = 0; it < 4; it++) {
        int idx = tid + it * 256;
        int n = idx >> 3, cc = idx & 7;
        cpa16(dstb + n * 128 + ((cc ^ (n & 7))) * 16, wsrc + (size_t)n * Dn + cc * 8);
    }
}

__global__ void __launch_bounds__(256, 1) maingemm_kernel(
    const float* __restrict__ x, const float* __restrict__ bias,
    const int* __restrict__ targets)
{
    const int tid  = threadIdx.x;
    const int lane = tid & 31;
    const int w    = tid >> 5;
    const int wm   = w >> 2;          // 0..1  (64 rows each)
    const int wn   = w & 3;           // 0..3  (32 cols each)
    const int cta  = blockIdx.x;

    const uint32_t sb = smem_u32(dynsm);
    const uint32_t As = sb + SM_A;
    const uint32_t Bs = sb + SM_B;
    float* sbias = (float*)(dynsm + SM_BIAS);
    float* lseb  = (float*)(dynsm + SM_RED);
    float* rawb  = (float*)(dynsm + SM_RED + 2048);

    // ---- bias -> smem once per persistent CTA ----
#pragma unroll
    for (int q = 0; q < 4; q++)
        ((float4*)sbias)[tid + q * 256] = ((const float4*)bias)[tid + q * 256];

    // ---- length-aware work partition ----
    int u    = g_ustart[cta];
    int uend = g_ustart[cta + 1];

    // ---- per-lane ldmatrix bases (fragment-invariant) ----
    const int arow = wm * 64 + (lane & 15);
    const uint32_t aBase = As + arow * 1024;
    const int alow = lane >> 4;
    const int arx  = arow & 7;
    const int bn   = wn * 32 + ((lane >> 4) << 3) + (lane & 7);
    const int bko  = (lane >> 3) & 1;
    const int bnx  = bn & 7;
    const bool blankown = (wn == 0) && ((lane & 3) == 0);

    uint32_t acc[2][4][4][2];         // double-buffered accumulators
#pragma unroll
    for (int pb = 0; pb < 2; pb++)
#pragma unroll
        for (int a0 = 0; a0 < 4; a0++)
#pragma unroll
            for (int b0 = 0; b0 < 4; b0++) { acc[pb][a0][b0][0] = 0u; acc[pb][a0][b0][1] = 0u; }
    float se[8], sr[8];
#pragma unroll
    for (int i = 0; i < 8; i++) { se[i] = 0.f; sr[i] = 0.f; }

    while (u < uend) {
        const int mt  = g_mtlist[u >> 5];
        const int vt0 = u & 31;
        int nvt = 32 - vt0;
        if (uend - u < nvt) nvt = uend - u;
        const int row0   = mt * 128;
        const int nch    = nvt * 8;
        const int cstart = vt0 * 8;

        // ---- per-fragment row ids + packed target selectors ----
        int grow[8]; int tkeyc[8];
#pragma unroll
        for (int i = 0; i < 8; i++) {
            int mtl = i >> 1, h = i & 1;
            int gr = row0 + wm * 64 + mtl * 16 + (lane >> 2) + h * 8;
            grow[i] = gr;
            int b = gr / BTU, rem = gr % BTU, uu = rem % U1n;
            int tv = (uu < U1n - 1) ? targets[b * (U1n - 1) + uu] : -1;
            int key = -1;
            if (tv >= 0 && ((tv >> 5) & 3) == wn && (((tv >> 1) & 3) == (lane & 3)))
                key = ((tv >> 3) << 1) | (tv & 1);     // (vt*16+wn*4+nt)<<1 | lo
            tkeyc[i] = key;
        }

        // deferred-epilogue state
        int pend = -1, pbuf = 0, abuf = 0;

        // epilogue for vtile vt_ from buffer A (then zero A)
        auto do_epi = [&](int vt_, uint32_t (&A)[4][4][2]) {
            float bcol[8];
#pragma unroll
            for (int nt = 0; nt < 4; nt++) {
                bcol[nt * 2]     = sbias[vt_ * 128 + wn * 32 + nt * 8 + (lane & 3) * 2];
                bcol[nt * 2 + 1] = sbias[vt_ * 128 + wn * 32 + nt * 8 + (lane & 3) * 2 + 1];
            }
            const int vbase = vt_ * 16 + wn * 4;
#pragma unroll
            for (int mtl = 0; mtl < 4; mtl++)
#pragma unroll
                for (int h = 0; h < 2; h++) {
                    const int i = mtl * 2 + h;
#pragma unroll
                    for (int nt = 0; nt < 4; nt++) {
                        uint32_t pk = A[mtl][nt][h];
                        float2 fv = __half22float2(*reinterpret_cast<__half2*>(&pk));
#pragma unroll
                        for (int lo = 0; lo < 2; lo++) {
                            float y = (lo ? fv.y : fv.x) + bcol[nt * 2 + lo];
                            sr[i] += y;
                            se[i] += exp2_fast(y * L2E);
                            if (tkeyc[i] == (((vbase + nt) << 1) | lo))
                                g_tgt[grow[i]] = y;
                            if (vt_ == 0 && nt == 0 && lo == 0 && blankown)
                                g_blank[grow[i]] = y;
                        }
                    }
                }
#pragma unroll
            for (int a0 = 0; a0 < 4; a0++)
#pragma unroll
                for (int b0 = 0; b0 < 4; b0++) { A[a0][b0][0] = 0u; A[a0][b0][1] = 0u; }
        };

        // ---- B prologue (stages 0,1) ----
        load_Bchunk(Bs, cstart, 0, tid);
        asm volatile("cp.async.commit_group;" ::: "memory");
        load_Bchunk(Bs, cstart + 1, 1, tid);
        asm volatile("cp.async.commit_group;" ::: "memory");

        // ---- fill A: fp32 -> fp16 into swizzled smem ----
#pragma unroll 4
        for (int it = 0; it < 32; it++) {
            int idx = tid + it * 256;
            int r = idx >> 6, ch = idx & 63;
            const float4* src = reinterpret_cast<const float4*>(
                x + (size_t)(row0 + r) * Dn + ch * 8);
            float4 v0 = src[0], v1 = src[1];
            __half2 p0 = __floats2half2_rn(v0.x, v0.y);
            __half2 p1 = __floats2half2_rn(v0.z, v0.w);
            __half2 p2 = __floats2half2_rn(v1.x, v1.y);
            __half2 p3 = __floats2half2_rn(v1.z, v1.w);
            uint32_t dchunk = (uint32_t)((ch & ~7) | ((ch ^ r) & 7));
            uint32_t dst = As + r * 1024 + dchunk * 16;
            asm volatile("st.shared.v4.b32 [%0], {%1,%2,%3,%4};" ::
                "r"(dst),
                "r"(*reinterpret_cast<uint32_t*>(&p0)), "r"(*reinterpret_cast<uint32_t*>(&p1)),
                "r"(*reinterpret_cast<uint32_t*>(&p2)), "r"(*reinterpret_cast<uint32_t*>(&p3))
                : "memory");
        }

        for (int ct = 0; ct < nch; ct++) {
            const int cg = cstart + ct;
            const int vt = cg >> 3, kc = cg & 7, st = ct % 3;
            __syncthreads();                       // stage (ct+2)%3 free / A-fill barrier
            if (ct + 2 < nch) {
                load_Bchunk(Bs, cstart + ct + 2, (ct + 2) % 3, tid);
                asm volatile("cp.async.commit_group;" ::: "memory");
                asm volatile("cp.async.wait_group 2;" ::: "memory");
            } else if (ct + 1 < nch) {
                asm volatile("cp.async.wait_group 1;" ::: "memory");
            } else {
                asm volatile("cp.async.wait_group 0;" ::: "memory");
            }
            __syncthreads();                       // chunk ct visible

            const uint32_t aCh = aBase + kc * 128;
            const uint32_t bSt = Bs + (uint32_t)st * 16384u + bn * 128;
#pragma unroll
            for (int ks = 0; ks < 4; ks++) {
                uint32_t afr[4][4];
#pragma unroll
                for (int mtl = 0; mtl < 4; mtl++) {
                    uint32_t ad = aCh + mtl * 16384 + (uint32_t)(((ks * 2 + alow) ^ arx)) * 16;
                    asm volatile("ldmatrix.sync.aligned.m8n8.x4.shared.b16 {%0,%1,%2,%3}, [%4];"
                        : "=r"(afr[mtl][0]), "=r"(afr[mtl][1]), "=r"(afr[mtl][2]), "=r"(afr[mtl][3])
                        : "r"(ad));
                }
                uint32_t bfr[2][4];
#pragma unroll
                for (int np = 0; np < 2; np++) {
                    uint32_t bd = bSt + np * 2048 + (uint32_t)(((ks * 2 + bko) ^ bnx)) * 16;
                    asm volatile("ldmatrix.sync.aligned.m8n8.x4.shared.b16 {%0,%1,%2,%3}, [%4];"
                        : "=r"(bfr[np][0]), "=r"(bfr[np][1]), "=r"(bfr[np][2]), "=r"(bfr[np][3])
                        : "r"(bd));
                }
                if (abuf == 0) {
#pragma unroll
                    for (int mtl = 0; mtl < 4; mtl++)
#pragma unroll
                        for (int nt = 0; nt < 4; nt++)
                            asm volatile("mma.sync.aligned.m16n8k16.row.col.f16.f16.f16.f16 "
                                "{%0,%1}, {%2,%3,%4,%5}, {%6,%7}, {%0,%1};"
                                : "+r"(acc[0][mtl][nt][0]), "+r"(acc[0][mtl][nt][1])
                                : "r"(afr[mtl][0]), "r"(afr[mtl][1]), "r"(afr[mtl][2]), "r"(afr[mtl][3]),
                                  "r"(bfr[nt >> 1][(nt & 1) * 2]), "r"(bfr[nt >> 1][(nt & 1) * 2 + 1]));
                } else {
#pragma unroll
                    for (int mtl = 0; mtl < 4; mtl++)
#pragma unroll
                        for (int nt = 0; nt < 4; nt++)
                            asm volatile("mma.sync.aligned.m16n8k16.row.col.f16.f16.f16.f16 "
                                "{%0,%1}, {%2,%3,%4,%5}, {%6,%7}, {%0,%1};"
                                : "+r"(acc[1][mtl][nt][0]), "+r"(acc[1][mtl][nt][1])
                                : "r"(afr[mtl][0]), "r"(afr[mtl][1]), "r"(afr[mtl][2]), "r"(afr[mtl][3]),
                                  "r"(bfr[nt >> 1][(nt & 1) * 2]), "r"(bfr[nt >> 1][(nt & 1) * 2 + 1]));
                }
            }

            if (kc == 7) {                      // vtile complete: hand off buffer
                pend = vt; pbuf = abuf; abuf ^= 1;
            } else if (kc == 0 && pend >= 0) {  // overlap epilogue with tensor work
                if (pbuf == 0) do_epi(pend, acc[0]); else do_epi(pend, acc[1]);
                pend = -1;
            }
        }
        // flush last vtile of this unit
        if (pend >= 0) { if (pbuf == 0) do_epi(pend, acc[0]); else do_epi(pend, acc[1]); }

        // ---- fragment partial reduction + slotted write ----
#pragma unroll
        for (int i = 0; i < 8; i++) {
            se[i] += __shfl_xor_sync(0xffffffffu, se[i], 1);
            se[i] += __shfl_xor_sync(0xffffffffu, se[i], 2);
            sr[i] += __shfl_xor_sync(0xffffffffu, sr[i], 1);
            sr[i] += __shfl_xor_sync(0xffffffffu, sr[i], 2);
        }
        __syncthreads();
        if ((lane & 3) == 0) {
#pragma unroll
            for (int i = 0; i < 8; i++) {
                int mtl = i >> 1, h = i & 1;
                int lr = wm * 64 + mtl * 16 + (lane >> 2) + h * 8;
                lseb[wn * 128 + lr] = se[i];
                rawb[wn * 128 + lr] = sr[i];
            }
        }
        __syncthreads();
        if (tid < 128) {
            float E = (lseb[tid] + lseb[128 + tid]) + (lseb[256 + tid] + lseb[384 + tid]);
            float R = (rawb[tid] + rawb[128 + tid]) + (rawb[256 + tid] + rawb[384 + tid]);
            // segment -> slot: start / end / middle (3-way splits possible)
            if (vt0 == 0)             { g_pE0[row0 + tid] = E; g_pR0[row0 + tid] = R; }
            else if (vt0 + nvt == 32) { g_pE1[row0 + tid] = E; g_pR1[row0 + tid] = R; }
            else                      { g_pE2[row0 + tid] = E; g_pR2[row0 + tid] = R; }
        }
#pragma unroll
        for (int i = 0; i < 8; i++) { se[i] = 0.f; sr[i] = 0.f; }

        u += nvt;
    }
}

// ---------------------------------------------------------------------------
// Kernel 2: per-batch DP, branch-free, log2 domain; 1024-thread staging
// ---------------------------------------------------------------------------
__global__ void __launch_bounds__(1024) finalize_kernel(
    const int* __restrict__ targets,
    const int* __restrict__ src_lengths,
    const int* __restrict__ tgt_lengths,
    float* __restrict__ out)
{
    __shared__ float sbl[BTUP];
    __shared__ float sem[BTUP];
    __shared__ float s_dp;
    const int b = blockIdx.x;
    const int tid = threadIdx.x;
    const int base = b * BTU;

    // stage lattice in log2 domain, stride-34 padded (bank-conflict-free DP)
    for (int i = tid; i < BTU; i += 1024) {
        int t = i / U1n, uu = i - t * U1n;
        float E = (g_pE0[base + i] + g_pE1[base + i]) + g_pE2[base + i];
        float l2 = lg2a(E);
        int p = t * U1P + uu;
        sbl[p] = fmaf(g_blank[base + i], L2E, -l2);
        sem[p] = fmaf(g_tgt[base + i],  L2E, -l2);
    }
    __syncthreads();

    if (tid < 32) {
        const int lane = tid;
        const int S  = src_lengths[b];
        const int TG = tgt_lengths[b];

        // ---- alpha0 via Kogge-Stone exclusive scan of sem[0..30] ----
        float v = sem[(lane == 0) ? 0 : (lane - 1)];
        v = (lane == 0) ? 0.f : v;
#pragma unroll
        for (int o = 1; o < 32; o <<= 1) {
            float nv = __shfl_up_sync(0xffffffffu, v, o);
            v += (lane >= o) ? nv : 0.f;
        }
        float cur  = v;                                        // alpha[0][lane]
        float cur2 = __shfl_sync(0xffffffffu, cur, 31) + sem[31];  // alpha[0][32]

        float afin = 0.f, haveF = 0.f;
        const int nsteps = (S - 1) + 32;
        for (int s = 1; s <= nsteps; s++) {
            float left   = __shfl_up_sync(0xffffffffu, cur, 1);
            float prev31 = cur;                                // lane31: alpha[t2][31]
            int t  = s - lane;
            int tc = max(1, min(t, S - 1));
            float up   = cur + sbl[(tc - 1) * U1P + lane];
            float alt  = left + sem[tc * U1P + ((lane == 0) ? 0 : (lane - 1))];
            float cand = laddexp2(up, alt);
            cand = (lane == 0) ? up : cand;
            bool valid = (t >= 1) && (t <= S - 1);
            cur = valid ? cand : cur;
            bool hit = valid && (t == S - 1) && (lane == TG);
            afin  = hit ? cur : afin;
            haveF = hit ? 1.f : haveF;
            int t2  = s - 32;
            int t2c = max(1, min(t2, S - 1));
            float up2   = cur2 + sbl[(t2c - 1) * U1P + 32];
            float alt2  = prev31 + sem[t2c * U1P + 31];
            float cand2 = laddexp2(up2, alt2);
            bool valid2 = (t2 >= 1) && (t2 <= S - 1);
            cur2 = valid2 ? cand2 : cur2;
            bool hit2 = valid2 && (t2 == S - 1) && (TG == 32) && (lane == 31);
            afin  = hit2 ? cur2 : afin;
            haveF = hit2 ? 1.f : haveF;
        }
        float lossb = -(afin + sbl[(S - 1) * U1P + TG]) * LN2 * haveF;
#pragma unroll
        for (int o = 16; o > 0; o >>= 1)
            lossb += __shfl_xor_sync(0xffffffffu, lossb, o);
        if (lane == 0) s_dp = lossb;
    }
    __syncthreads();

    if (tid < 32) {
        const int uu = tid;
        const int S = src_lengths[b];
        const int tv = targets[b * (U1n - 1) + uu];
        const int row = b * BTU + (S - 1) * U1n + uu;
        float E = (g_pE0[row] + g_pE1[row]) + g_pE2[row];
        float lse = lg2a(E) * LN2;
        float R = (g_pR0[row] + g_pR1[row]) + g_pR2[row];
        float nll = lse - g_tgt[row];
        float smooth = (float)Vn * lse - R;
        const float LS = 0.1f;
        const float eps = LS / (float)(Vn - 1);
        float m = (tv != 1) ? 1.f : 0.f;
        float term = ((1.f - LS - eps) * nll + eps * smooth) * m;
#pragma unroll
        for (int o = 16; o > 0; o >>= 1)
            term += __shfl_xor_sync(0xffffffffu, term, o);
        if (uu == 0) {
            g_part[b] = s_dp + term;
            __threadfence();
            unsigned t = atomicAdd(&g_done, 1u);
            if (t == (unsigned)(Bn - 1)) {
                __threadfence();
                float s = 0.f;
#pragma unroll
                for (int bb = 0; bb < Bn; bb++) s += g_part[bb];
                out[0] = s;
                g_done = 0u;           // reset for next graph replay
            }
        }
    }
}

// ---------------------------------------------------------------------------
extern "C" void kernel_launch(void* const* d_in, const int* in_sizes, int n_in,
                              void* d_out, int out_size)
{
    const float* x       = (const float*)d_in[0];
    const float* wgt     = (const float*)d_in[1];
    const float* bias    = (const float*)d_in[2];
    const int*   targets = (const int*)d_in[3];
    const int*   src     = (const int*)d_in[4];
    const int*   tgt     = (const int*)d_in[5];
    float* out = (float*)d_out;

    static bool attr_set = false;
    if (!attr_set) {
        cudaFuncSetAttribute(maingemm_kernel,
                             cudaFuncAttributeMaxDynamicSharedMemorySize, SM_TOT);
        attr_set = true;
    }

    convW_kernel<<<1025, 256>>>(wgt, src);
    maingemm_kernel<<<NCTA, 256, SM_TOT>>>(x, bias, targets);
    finalize_kernel<<<Bn, 1024>>>(targets, src, tgt, out);
}

// round 16
// speedup vs baseline: 1.0160x; 1.0160x over previous
#include <cuda_runtime.h>
#include <cuda_fp16.h>
#include <math.h>
#include <stdint.h>

#define Bn   8
#define Tn   128
#define U1n  33
#define Dn   512
#define Vn   4096
#define BTU  (Tn*U1n)          // 4224
#define ROWS (Bn*BTU)          // 33792
#define MTL  (ROWS/128)        // 264 M-tiles (33 per batch)
#define NVT  (Vn/128)          // 32 vocab tiles
#define NCTA 148
#define L2E  1.442695040888963f
#define LN2  0.6931471805599453f
#define U1P  34                // padded lattice stride (bank-conflict-free)
#define BTUP (Tn*U1P)          // 4352

// smem layout (bytes) for maingemm
#define SM_A     0u            // 128 x 512 fp16 = 131072
#define SM_B     131072u       // 3 stages x 16384 (128n x 64k fp16)
#define SM_BIAS  180224u       // 4096 floats = 16384
#define SM_RED   196608u       // 2 x 512 floats = 4096
#define SM_TOT   200704u

// ---------------- device scratch ----------------
__device__ __align__(16) __half g_Wh[(size_t)Vn*Dn];
__device__ float g_pE0[ROWS];   // start segments (vt0 == 0)
__device__ float g_pE1[ROWS];   // end segments (vt0 > 0, reaches vtile 31)
__device__ float g_pE2[ROWS];   // middle segments (rare 3-way splits)
__device__ float g_pR0[ROWS];
__device__ float g_pR1[ROWS];
__device__ float g_pR2[ROWS];
__device__ float g_blank[ROWS];
__device__ float g_tgt[ROWS];
__device__ float g_part[Bn];
__device__ unsigned g_done;
__device__ int g_mtlist[MTL];          // useful mtile ids
__device__ int g_ustart[NCTA + 1];     // per-CTA unit ranges

// ---------------- helpers ----------------
__device__ __forceinline__ uint32_t smem_u32(const void* p) {
    uint32_t a;
    asm("{ .reg .u64 t; cvta.to.shared.u64 t, %1; cvt.u32.u64 %0, t; }" : "=r"(a) : "l"(p));
    return a;
}
__device__ __forceinline__ void cpa16(uint32_t dst, const void* src) {
    asm volatile("cp.async.cg.shared.global [%0], [%1], 16;" :: "r"(dst), "l"(src));
}
__device__ __forceinline__ float ex2a(float x) {
    float y; asm("ex2.approx.ftz.f32 %0, %1;" : "=f"(y) : "f"(x)); return y;
}
__device__ __forceinline__ float lg2a(float x) {
    float y; asm("lg2.approx.ftz.f32 %0, %1;" : "=f"(y) : "f"(x)); return y;
}
// log2-domain logaddexp: max + lg2(1 + 2^(min-max)). MUFU-only, short chain.
__device__ __forceinline__ float laddexp2(float a, float b) {
    float m = fmaxf(a, b);
    float d = fminf(a, b) - m;
    return m + lg2a(1.0f + ex2a(d));
}
// fast 2^z, FFMA-only (no MUFU). |rel err| ~2e-6.
__device__ __forceinline__ float exp2_fast(float z) {
    float zc = z + 12582912.f;
    int   ni = __float_as_int(zc);
    float n  = zc - 12582912.f;
    float f  = z - n;
    float p  = fmaf(0.0013333558f, f, 0.0096181291f);
    p = fmaf(p, f, 0.0555041087f);
    p = fmaf(p, f, 0.2402265069f);
    p = fmaf(p, f, 0.6931471806f);
    p = fmaf(p, f, 1.0f);
    return __int_as_float(__float_as_int(p) + (ni << 23));
}

// ---------------------------------------------------------------------------
// Kernel 0: convert W fp32 -> fp16
// ---------------------------------------------------------------------------
__global__ void __launch_bounds__(256) convW_kernel(const float* __restrict__ w)
{
    int i = blockIdx.x * 256 + threadIdx.x;          // each handles 8 floats
    const float4* src = reinterpret_cast<const float4*>(w) + (size_t)i * 2;
    float4 v0 = src[0], v1 = src[1];
    __half2 p0 = __floats2half2_rn(v0.x, v0.y);
    __half2 p1 = __floats2half2_rn(v0.z, v0.w);
    __half2 p2 = __floats2half2_rn(v1.x, v1.y);
    __half2 p3 = __floats2half2_rn(v1.z, v1.w);
    uint4 o;
    o.x = *reinterpret_cast<uint32_t*>(&p0);
    o.y = *reinterpret_cast<uint32_t*>(&p1);
    o.z = *reinterpret_cast<uint32_t*>(&p2);
    o.w = *reinterpret_cast<uint32_t*>(&p3);
    *reinterpret_cast<uint4*>(g_Wh + (size_t)i * 8) = o;
}

// ---------------------------------------------------------------------------
// Kernel 0b: build useful-mtile list + balanced per-CTA unit partition.
// Deterministic (function of src_lengths only) -> identical every replay.
// ---------------------------------------------------------------------------
__global__ void schedule_kernel(const int* __restrict__ src)
{
    if (threadIdx.x != 0) return;
    int S[Bn];
#pragma unroll
    for (int b = 0; b < Bn; b++) S[b] = src[b];
    int n = 0;
    for (int mt = 0; mt < MTL; mt++) {
        int b = mt / 33, m = mt % 33;
        if ((m * 128) / 33 < S[b]) g_mtlist[n++] = mt;   // mtile has a row with t < S
    }
    int utot = n * NVT;
    int ub = utot / NCTA, ur = utot % NCTA;
    int acc = 0;
    for (int c = 0; c <= NCTA; c++) {
        g_ustart[c] = acc;
        acc += ub + (c < ur ? 1 : 0);
    }
}

// ---------------------------------------------------------------------------
// Kernel 1: persistent fp16 mma.sync GEMM + fused statistics
//   148 CTAs x 256 threads; length-aware unit partition over (mtile, vtile)
// ---------------------------------------------------------------------------
extern __shared__ char dynsm[];

__device__ __forceinline__ void load_Bchunk(uint32_t Bs, int cg, int stage, int tid)
{
    const __half* wsrc = g_Wh + ((size_t)(cg >> 3)) * 128 * Dn + (cg & 7) * 64;
    const uint32_t dstb = Bs + (uint32_t)stage * 16384u;
#pragma unroll
    for (int it = 0; it < 4; it++) {
        int idx = tid + it * 256;
        int n = idx >> 3, cc = idx & 7;
        cpa16(dstb + n * 128 + ((cc ^ (n & 7))) * 16, wsrc + (size_t)n * Dn + cc * 8);
    }
}

__global__ void __launch_bounds__(256, 1) maingemm_kernel(
    const float* __restrict__ x, const float* __restrict__ bias,
    const int* __restrict__ targets)
{
    const int tid  = threadIdx.x;
    const int lane = tid & 31;
    const int w    = tid >> 5;
    const int wm   = w >> 2;          // 0..1  (64 rows each)
    const int wn   = w & 3;           // 0..3  (32 cols each)
    const int cta  = blockIdx.x;

    const uint32_t sb = smem_u32(dynsm);
    const uint32_t As = sb + SM_A;
    const uint32_t Bs = sb + SM_B;
    float* sbias = (float*)(dynsm + SM_BIAS);
    float* lseb  = (float*)(dynsm + SM_RED);
    float* rawb  = (float*)(dynsm + SM_RED + 2048);

    // ---- bias -> smem once per persistent CTA ----
#pragma unroll
    for (int q = 0; q < 4; q++)
        ((float4*)sbias)[tid + q * 256] = ((const float4*)bias)[tid + q * 256];

    // ---- length-aware work partition (from schedule_kernel) ----
    int u    = g_ustart[cta];
    int uend = g_ustart[cta + 1];

    // ---- per-lane ldmatrix bases (fragment-invariant) ----
    const int arow = wm * 64 + (lane & 15);
    const uint32_t aBase = As + arow * 1024;
    const int alow = lane >> 4;
    const int arx  = arow & 7;
    const int bn   = wn * 32 + ((lane >> 4) << 3) + (lane & 7);
    const int bko  = (lane >> 3) & 1;
    const int bnx  = bn & 7;
    const bool blankown = (wn == 0) && ((lane & 3) == 0);

    uint32_t acc[4][4][2];
#pragma unroll
    for (int a0 = 0; a0 < 4; a0++)
#pragma unroll
        for (int b0 = 0; b0 < 4; b0++) { acc[a0][b0][0] = 0u; acc[a0][b0][1] = 0u; }
    float se[8], sr[8];
#pragma unroll
    for (int i = 0; i < 8; i++) { se[i] = 0.f; sr[i] = 0.f; }

    while (u < uend) {
        const int mt  = g_mtlist[u >> 5];
        const int vt0 = u & 31;
        int nvt = 32 - vt0;
        if (uend - u < nvt) nvt = uend - u;
        const int row0   = mt * 128;
        const int nch    = nvt * 8;
        const int cstart = vt0 * 8;

        // ---- per-fragment row ids + target selectors ----
        int grow[8]; int tkey[8]; int tlo[8];
#pragma unroll
        for (int i = 0; i < 8; i++) {
            int mtl = i >> 1, h = i & 1;
            int gr = row0 + wm * 64 + mtl * 16 + (lane >> 2) + h * 8;
            grow[i] = gr;
            int b = gr / BTU, rem = gr % BTU, uu = rem % U1n;
            int tv = (uu < U1n - 1) ? targets[b * (U1n - 1) + uu] : -1;
            int key = -1, lo = 0;
            if (tv >= 0 && ((tv >> 5) & 3) == wn && (((tv >> 1) & 3) == (lane & 3))) {
                key = tv >> 3;
                lo  = tv & 1;
            }
            tkey[i] = key; tlo[i] = lo;
        }

        // ---- B prologue (stages 0,1) ----
        load_Bchunk(Bs, cstart, 0, tid);
        asm volatile("cp.async.commit_group;" ::: "memory");
        load_Bchunk(Bs, cstart + 1, 1, tid);
        asm volatile("cp.async.commit_group;" ::: "memory");

        // ---- fill A: fp32 -> fp16 into swizzled smem ----
#pragma unroll 4
        for (int it = 0; it < 32; it++) {
            int idx = tid + it * 256;
            int r = idx >> 6, ch = idx & 63;
            const float4* src = reinterpret_cast<const float4*>(
                x + (size_t)(row0 + r) * Dn + ch * 8);
            float4 v0 = src[0], v1 = src[1];
            __half2 p0 = __floats2half2_rn(v0.x, v0.y);
            __half2 p1 = __floats2half2_rn(v0.z, v0.w);
            __half2 p2 = __floats2half2_rn(v1.x, v1.y);
            __half2 p3 = __floats2half2_rn(v1.z, v1.w);
            uint32_t dchunk = (uint32_t)((ch & ~7) | ((ch ^ r) & 7));
            uint32_t dst = As + r * 1024 + dchunk * 16;
            asm volatile("st.shared.v4.b32 [%0], {%1,%2,%3,%4};" ::
                "r"(dst),
                "r"(*reinterpret_cast<uint32_t*>(&p0)), "r"(*reinterpret_cast<uint32_t*>(&p1)),
                "r"(*reinterpret_cast<uint32_t*>(&p2)), "r"(*reinterpret_cast<uint32_t*>(&p3))
                : "memory");
        }

        for (int ct = 0; ct < nch; ct++) {
            const int cg = cstart + ct;
            const int vt = cg >> 3, kc = cg & 7, st = ct % 3;
            __syncthreads();                       // stage (ct+2)%3 free / A-fill barrier
            if (ct + 2 < nch) {
                load_Bchunk(Bs, cstart + ct + 2, (ct + 2) % 3, tid);
                asm volatile("cp.async.commit_group;" ::: "memory");
                asm volatile("cp.async.wait_group 2;" ::: "memory");
            } else if (ct + 1 < nch) {
                asm volatile("cp.async.wait_group 1;" ::: "memory");
            } else {
                asm volatile("cp.async.wait_group 0;" ::: "memory");
            }
            __syncthreads();                       // chunk ct visible

            const uint32_t aCh = aBase + kc * 128;
            const uint32_t bSt = Bs + (uint32_t)st * 16384u + bn * 128;
#pragma unroll
            for (int ks = 0; ks < 4; ks++) {
                uint32_t afr[4][4];
#pragma unroll
                for (int mtl = 0; mtl < 4; mtl++) {
                    uint32_t ad = aCh + mtl * 16384 + (uint32_t)(((ks * 2 + alow) ^ arx)) * 16;
                    asm volatile("ldmatrix.sync.aligned.m8n8.x4.shared.b16 {%0,%1,%2,%3}, [%4];"
                        : "=r"(afr[mtl][0]), "=r"(afr[mtl][1]), "=r"(afr[mtl][2]), "=r"(afr[mtl][3])
                        : "r"(ad));
                }
                uint32_t bfr[2][4];
#pragma unroll
                for (int np = 0; np < 2; np++) {
                    uint32_t bd = bSt + np * 2048 + (uint32_t)(((ks * 2 + bko) ^ bnx)) * 16;
                    asm volatile("ldmatrix.sync.aligned.m8n8.x4.shared.b16 {%0,%1,%2,%3}, [%4];"
                        : "=r"(bfr[np][0]), "=r"(bfr[np][1]), "=r"(bfr[np][2]), "=r"(bfr[np][3])
                        : "r"(bd));
                }
#pragma unroll
                for (int mtl = 0; mtl < 4; mtl++)
#pragma unroll
                    for (int nt = 0; nt < 4; nt++) {
                        asm volatile("mma.sync.aligned.m16n8k16.row.col.f16.f16.f16.f16 "
                            "{%0,%1}, {%2,%3,%4,%5}, {%6,%7}, {%0,%1};"
                            : "+r"(acc[mtl][nt][0]), "+r"(acc[mtl][nt][1])
                            : "r"(afr[mtl][0]), "r"(afr[mtl][1]), "r"(afr[mtl][2]), "r"(afr[mtl][3]),
                              "r"(bfr[nt >> 1][(nt & 1) * 2]), "r"(bfr[nt >> 1][(nt & 1) * 2 + 1]));
                    }
            }

            if (kc == 7) {
                // ---- register-only epilogue for vtile vt ----
                float bcol[8];
#pragma unroll
                for (int nt = 0; nt < 4; nt++) {
                    bcol[nt * 2]     = sbias[vt * 128 + wn * 32 + nt * 8 + (lane & 3) * 2];
                    bcol[nt * 2 + 1] = sbias[vt * 128 + wn * 32 + nt * 8 + (lane & 3) * 2 + 1];
                }
                const int vbase = vt * 16 + wn * 4;
#pragma unroll
                for (int mtl = 0; mtl < 4; mtl++)
#pragma unroll
                    for (int h = 0; h < 2; h++) {
                        const int i = mtl * 2 + h;
#pragma unroll
                        for (int nt = 0; nt < 4; nt++) {
                            uint32_t pk = acc[mtl][nt][h];
                            float2 fv = __half22float2(*reinterpret_cast<__half2*>(&pk));
#pragma unroll
                            for (int lo = 0; lo < 2; lo++) {
                                float y = (lo ? fv.y : fv.x) + bcol[nt * 2 + lo];
                                sr[i] += y;
                                se[i] += exp2_fast(y * L2E);
                                if (tkey[i] == vbase + nt && tlo[i] == lo)
                                    g_tgt[grow[i]] = y;
                                if (vt == 0 && nt == 0 && lo == 0 && blankown)
                                    g_blank[grow[i]] = y;
                            }
                        }
                    }
#pragma unroll
                for (int a0 = 0; a0 < 4; a0++)
#pragma unroll
                    for (int b0 = 0; b0 < 4; b0++) { acc[a0][b0][0] = 0u; acc[a0][b0][1] = 0u; }
            }
        }

        // ---- fragment partial reduction + slotted write ----
#pragma unroll
        for (int i = 0; i < 8; i++) {
            se[i] += __shfl_xor_sync(0xffffffffu, se[i], 1);
            se[i] += __shfl_xor_sync(0xffffffffu, se[i], 2);
            sr[i] += __shfl_xor_sync(0xffffffffu, sr[i], 1);
            sr[i] += __shfl_xor_sync(0xffffffffu, sr[i], 2);
        }
        __syncthreads();
        if ((lane & 3) == 0) {
#pragma unroll
            for (int i = 0; i < 8; i++) {
                int mtl = i >> 1, h = i & 1;
                int lr = wm * 64 + mtl * 16 + (lane >> 2) + h * 8;
                lseb[wn * 128 + lr] = se[i];
                rawb[wn * 128 + lr] = sr[i];
            }
        }
        __syncthreads();
        if (tid < 128) {
            float E = (lseb[tid] + lseb[128 + tid]) + (lseb[256 + tid] + lseb[384 + tid]);
            float R = (rawb[tid] + rawb[128 + tid]) + (rawb[256 + tid] + rawb[384 + tid]);
            // segment -> slot: start / end / middle (3-way splits possible)
            if (vt0 == 0)             { g_pE0[row0 + tid] = E; g_pR0[row0 + tid] = R; }
            else if (vt0 + nvt == 32) { g_pE1[row0 + tid] = E; g_pR1[row0 + tid] = R; }
            else                      { g_pE2[row0 + tid] = E; g_pR2[row0 + tid] = R; }
        }
#pragma unroll
        for (int i = 0; i < 8; i++) { se[i] = 0.f; sr[i] = 0.f; }

        u += nvt;
    }
}

// ---------------------------------------------------------------------------
// Kernel 2: per-batch DP, branch-free, log2 domain; 1024-thread staging
// ---------------------------------------------------------------------------
__global__ void __launch_bounds__(1024) finalize_kernel(
    const int* __restrict__ targets,
    const int* __restrict__ src_lengths,
    const int* __restrict__ tgt_lengths,
    float* __restrict__ out)
{
    __shared__ float sbl[BTUP];
    __shared__ float sem[BTUP];
    __shared__ float s_dp;
    const int b = blockIdx.x;
    const int tid = threadIdx.x;
    const int base = b * BTU;

    // stage lattice in log2 domain, stride-34 padded (bank-conflict-free DP)
    for (int i = tid; i < BTU; i += 1024) {
        int t = i / U1n, uu = i - t * U1n;
        float E = (g_pE0[base + i] + g_pE1[base + i]) + g_pE2[base + i];
        float l2 = lg2a(E);
        int p = t * U1P + uu;
        sbl[p] = fmaf(g_blank[base + i], L2E, -l2);
        sem[p] = fmaf(g_tgt[base + i],  L2E, -l2);
    }
    __syncthreads();

    if (tid < 32) {
        const int lane = tid;
        const int S  = src_lengths[b];
        const int TG = tgt_lengths[b];

        // ---- alpha0 via Kogge-Stone exclusive scan of sem[0..30] ----
        float v = sem[(lane == 0) ? 0 : (lane - 1)];
        v = (lane == 0) ? 0.f : v;
#pragma unroll
        for (int o = 1; o < 32; o <<= 1) {
            float nv = __shfl_up_sync(0xffffffffu, v, o);
            v += (lane >= o) ? nv : 0.f;
        }
        float cur  = v;                                        // alpha[0][lane]
        float cur2 = __shfl_sync(0xffffffffu, cur, 31) + sem[31];  // alpha[0][32]

        float afin = 0.f, haveF = 0.f;
        const int nsteps = (S - 1) + 32;
        for (int s = 1; s <= nsteps; s++) {
            float left   = __shfl_up_sync(0xffffffffu, cur, 1);
            float prev31 = cur;                                // lane31: alpha[t2][31]
            int t  = s - lane;
            int tc = max(1, min(t, S - 1));
            float up   = cur + sbl[(tc - 1) * U1P + lane];
            float alt  = left + sem[tc * U1P + ((lane == 0) ? 0 : (lane - 1))];
            float cand = laddexp2(up, alt);
            cand = (lane == 0) ? up : cand;
            bool valid = (t >= 1) && (t <= S - 1);
            cur = valid ? cand : cur;
            bool hit = valid && (t == S - 1) && (lane == TG);
            afin  = hit ? cur : afin;
            haveF = hit ? 1.f : haveF;
            // column u=32: computed by all lanes; only lane31's value is real
            int t2  = s - 32;
            int t2c = max(1, min(t2, S - 1));
            float up2   = cur2 + sbl[(t2c - 1) * U1P + 32];
            float alt2  = prev31 + sem[t2c * U1P + 31];
            float cand2 = laddexp2(up2, alt2);
            bool valid2 = (t2 >= 1) && (t2 <= S - 1);
            cur2 = valid2 ? cand2 : cur2;
            bool hit2 = valid2 && (t2 == S - 1) && (TG == 32) && (lane == 31);
            afin  = hit2 ? cur2 : afin;
            haveF = hit2 ? 1.f : haveF;
        }
        float lossb = -(afin + sbl[(S - 1) * U1P + TG]) * LN2 * haveF;
#pragma unroll
        for (int o = 16; o > 0; o >>= 1)
            lossb += __shfl_xor_sync(0xffffffffu, lossb, o);
        if (lane == 0) s_dp = lossb;
    }
    __syncthreads();

    if (tid < 32) {
        const int uu = tid;
        const int S = src_lengths[b];
        const int tv = targets[b * (U1n - 1) + uu];
        const int row = b * BTU + (S - 1) * U1n + uu;
        float E = (g_pE0[row] + g_pE1[row]) + g_pE2[row];
        float lse = lg2a(E) * LN2;
        float R = (g_pR0[row] + g_pR1[row]) + g_pR2[row];
        float nll = lse - g_tgt[row];
        float smooth = (float)Vn * lse - R;
        const float LS = 0.1f;
        const float eps = LS / (float)(Vn - 1);
        float m = (tv != 1) ? 1.f : 0.f;
        float term = ((1.f - LS - eps) * nll + eps * smooth) * m;
#pragma unroll
        for (int o = 16; o > 0; o >>= 1)
            term += __shfl_xor_sync(0xffffffffu, term, o);
        if (uu == 0) {
            g_part[b] = s_dp + term;
            __threadfence();
            unsigned t = atomicAdd(&g_done, 1u);
            if (t == (unsigned)(Bn - 1)) {
                __threadfence();
                float s = 0.f;
#pragma unroll
                for (int bb = 0; bb < Bn; bb++) s += g_part[bb];
                out[0] = s;
                g_done = 0u;           // reset for next graph replay
            }
        }
    }
}

// ---------------------------------------------------------------------------
extern "C" void kernel_launch(void* const* d_in, const int* in_sizes, int n_in,
                              void* d_out, int out_size)
{
    const float* x       = (const float*)d_in[0];
    const float* wgt     = (const float*)d_in[1];
    const float* bias    = (const float*)d_in[2];
    const int*   targets = (const int*)d_in[3];
    const int*   src     = (const int*)d_in[4];
    const int*   tgt     = (const int*)d_in[5];
    float* out = (float*)d_out;

    static bool attr_set = false;
    if (!attr_set) {
        cudaFuncSetAttribute(maingemm_kernel,
                             cudaFuncAttributeMaxDynamicSharedMemorySize, SM_TOT);
        attr_set = true;
    }

    convW_kernel<<<(Vn * Dn / 8) / 256, 256>>>(wgt);
    schedule_kernel<<<1, 32>>>(src);
    maingemm_kernel<<<NCTA, 256, SM_TOT>>>(x, bias, targets);
    finalize_kernel<<<Bn, 1024>>>(targets, src, tgt, out);
}

// round 17
// speedup vs baseline: 1.0689x; 1.0522x over previous
#include <cuda_runtime.h>
#include <cuda_fp16.h>
#include <math.h>
#include <stdint.h>

#define Bn   8
#define Tn   128
#define U1n  33
#define Dn   512
#define Vn   4096
#define BTU  (Tn*U1n)          // 4224
#define ROWS (Bn*BTU)          // 33792
#define MTL  (ROWS/128)        // 264 M-tiles (33 per batch)
#define NVT  (Vn/128)          // 32 vocab tiles
#define NCTA 148
#define L2E  1.442695040888963f
#define LN2  0.6931471805599453f
#define U1P  34                // padded lattice stride (bank-conflict-free)
#define BTUP (Tn*U1P)          // 4352

// smem layout (bytes) for maingemm
#define SM_A     0u            // 128 x 512 fp16 = 131072
#define SM_B     131072u       // 3 stages x 16384 (128n x 64k fp16)
#define SM_BIAS  180224u       // 4096 floats = 16384
#define SM_RED   196608u       // 2 x 512 floats = 4096
#define SM_TOT   200704u

// finalize dynamic smem: sbl/sem (padded) + 5 staged arrays
#define FSM_BYTES ((2*BTUP + 5*BTU) * 4)   // 119296

// ---------------- device scratch ----------------
__device__ __align__(16) __half g_Wh[(size_t)Vn*Dn];
__device__ __align__(16) float g_pE0[ROWS];   // start segments (vt0 == 0)
__device__ __align__(16) float g_pE1[ROWS];   // end segments
__device__ __align__(16) float g_pE2[ROWS];   // middle segments (rare)
__device__ __align__(16) float g_pR0[ROWS];
__device__ __align__(16) float g_pR1[ROWS];
__device__ __align__(16) float g_pR2[ROWS];
__device__ __align__(16) float g_blank[ROWS];
__device__ __align__(16) float g_tgt[ROWS];
__device__ float g_part[Bn];
__device__ unsigned g_done;
__device__ int g_mtlist[MTL];          // useful mtile ids
__device__ int g_ustart[NCTA + 1];     // per-CTA unit ranges

// ---------------- helpers ----------------
__device__ __forceinline__ uint32_t smem_u32(const void* p) {
    uint32_t a;
    asm("{ .reg .u64 t; cvta.to.shared.u64 t, %1; cvt.u32.u64 %0, t; }" : "=r"(a) : "l"(p));
    return a;
}
__device__ __forceinline__ void cpa16(uint32_t dst, const void* src) {
    asm volatile("cp.async.cg.shared.global [%0], [%1], 16;" :: "r"(dst), "l"(src));
}
__device__ __forceinline__ float ex2a(float x) {
    float y; asm("ex2.approx.ftz.f32 %0, %1;" : "=f"(y) : "f"(x)); return y;
}
__device__ __forceinline__ float lg2a(float x) {
    float y; asm("lg2.approx.ftz.f32 %0, %1;" : "=f"(y) : "f"(x)); return y;
}
// log2-domain logaddexp: max + lg2(1 + 2^(min-max)). MUFU-only, short chain.
__device__ __forceinline__ float laddexp2(float a, float b) {
    float m = fmaxf(a, b);
    float d = fminf(a, b) - m;
    return m + lg2a(1.0f + ex2a(d));
}
// fast 2^z, FFMA-only (no MUFU). |rel err| ~2e-6.
__device__ __forceinline__ float exp2_fast(float z) {
    float zc = z + 12582912.f;
    int   ni = __float_as_int(zc);
    float n  = zc - 12582912.f;
    float f  = z - n;
    float p  = fmaf(0.0013333558f, f, 0.0096181291f);
    p = fmaf(p, f, 0.0555041087f);
    p = fmaf(p, f, 0.2402265069f);
    p = fmaf(p, f, 0.6931471806f);
    p = fmaf(p, f, 1.0f);
    return __int_as_float(__float_as_int(p) + (ni << 23));
}

// ---------------------------------------------------------------------------
// Kernel 0: convert W fp32 -> fp16
// ---------------------------------------------------------------------------
__global__ void __launch_bounds__(256) convW_kernel(const float* __restrict__ w)
{
    int i = blockIdx.x * 256 + threadIdx.x;          // each handles 8 floats
    const float4* src = reinterpret_cast<const float4*>(w) + (size_t)i * 2;
    float4 v0 = src[0], v1 = src[1];
    __half2 p0 = __floats2half2_rn(v0.x, v0.y);
    __half2 p1 = __floats2half2_rn(v0.z, v0.w);
    __half2 p2 = __floats2half2_rn(v1.x, v1.y);
    __half2 p3 = __floats2half2_rn(v1.z, v1.w);
    uint4 o;
    o.x = *reinterpret_cast<uint32_t*>(&p0);
    o.y = *reinterpret_cast<uint32_t*>(&p1);
    o.z = *reinterpret_cast<uint32_t*>(&p2);
    o.w = *reinterpret_cast<uint32_t*>(&p3);
    *reinterpret_cast<uint4*>(g_Wh + (size_t)i * 8) = o;
}

// ---------------------------------------------------------------------------
// Kernel 0b: build useful-mtile list + balanced per-CTA unit partition.
// Deterministic (function of src_lengths only) -> identical every replay.
// ---------------------------------------------------------------------------
__global__ void schedule_kernel(const int* __restrict__ src)
{
    if (threadIdx.x != 0) return;
    int S[Bn];
#pragma unroll
    for (int b = 0; b < Bn; b++) S[b] = src[b];
    int n = 0;
    for (int mt = 0; mt < MTL; mt++) {
        int b = mt / 33, m = mt % 33;
        if ((m * 128) / 33 < S[b]) g_mtlist[n++] = mt;   // mtile has a row with t < S
    }
    int utot = n * NVT;
    int ub = utot / NCTA, ur = utot % NCTA;
    int acc = 0;
    for (int c = 0; c <= NCTA; c++) {
        g_ustart[c] = acc;
        acc += ub + (c < ur ? 1 : 0);
    }
}

// ---------------------------------------------------------------------------
// Kernel 1: persistent fp16 mma.sync GEMM + fused statistics
//   148 CTAs x 256 threads; single barrier per chunk (combined publish+reuse)
// ---------------------------------------------------------------------------
extern __shared__ char dynsm[];

__device__ __forceinline__ void load_Bchunk(uint32_t Bs, int cg, int stage, int tid)
{
    const __half* wsrc = g_Wh + ((size_t)(cg >> 3)) * 128 * Dn + (cg & 7) * 64;
    const uint32_t dstb = Bs + (uint32_t)stage * 16384u;
#pragma unroll
    for (int it = 0; it < 4; it++) {
        int idx = tid + it * 256;
        int n = idx >> 3, cc = idx & 7;
        cpa16(dstb + n * 128 + ((cc ^ (n & 7))) * 16, wsrc + (size_t)n * Dn + cc * 8);
    }
}

__global__ void __launch_bounds__(256, 1) maingemm_kernel(
    const float* __restrict__ x, const float* __restrict__ bias,
    const int* __restrict__ targets)
{
    const int tid  = threadIdx.x;
    const int lane = tid & 31;
    const int w    = tid >> 5;
    const int wm   = w >> 2;          // 0..1  (64 rows each)
    const int wn   = w & 3;           // 0..3  (32 cols each)
    const int cta  = blockIdx.x;

    const uint32_t sb = smem_u32(dynsm);
    const uint32_t As = sb + SM_A;
    const uint32_t Bs = sb + SM_B;
    float* sbias = (float*)(dynsm + SM_BIAS);
    float* lseb  = (float*)(dynsm + SM_RED);
    float* rawb  = (float*)(dynsm + SM_RED + 2048);

    // ---- bias -> smem once per persistent CTA ----
#pragma unroll
    for (int q = 0; q < 4; q++)
        ((float4*)sbias)[tid + q * 256] = ((const float4*)bias)[tid + q * 256];

    // ---- length-aware work partition (from schedule_kernel) ----
    int u    = g_ustart[cta];
    int uend = g_ustart[cta + 1];

    // ---- per-lane ldmatrix bases (fragment-invariant) ----
    const int arow = wm * 64 + (lane & 15);
    const uint32_t aBase = As + arow * 1024;
    const int alow = lane >> 4;
    const int arx  = arow & 7;
    const int bn   = wn * 32 + ((lane >> 4) << 3) + (lane & 7);
    const int bko  = (lane >> 3) & 1;
    const int bnx  = bn & 7;
    const bool blankown = (wn == 0) && ((lane & 3) == 0);

    uint32_t acc[4][4][2];
#pragma unroll
    for (int a0 = 0; a0 < 4; a0++)
#pragma unroll
        for (int b0 = 0; b0 < 4; b0++) { acc[a0][b0][0] = 0u; acc[a0][b0][1] = 0u; }
    float se[8], sr[8];
#pragma unroll
    for (int i = 0; i < 8; i++) { se[i] = 0.f; sr[i] = 0.f; }

    while (u < uend) {
        const int mt  = g_mtlist[u >> 5];
        const int vt0 = u & 31;
        int nvt = 32 - vt0;
        if (uend - u < nvt) nvt = uend - u;
        const int row0   = mt * 128;
        const int nch    = nvt * 8;
        const int cstart = vt0 * 8;

        // ---- per-fragment row ids + target selectors ----
        int grow[8]; int tkey[8]; int tlo[8];
#pragma unroll
        for (int i = 0; i < 8; i++) {
            int mtl = i >> 1, h = i & 1;
            int gr = row0 + wm * 64 + mtl * 16 + (lane >> 2) + h * 8;
            grow[i] = gr;
            int b = gr / BTU, rem = gr % BTU, uu = rem % U1n;
            int tv = (uu < U1n - 1) ? targets[b * (U1n - 1) + uu] : -1;
            int key = -1, lo = 0;
            if (tv >= 0 && ((tv >> 5) & 3) == wn && (((tv >> 1) & 3) == (lane & 3))) {
                key = tv >> 3;
                lo  = tv & 1;
            }
            tkey[i] = key; tlo[i] = lo;
        }

        // ---- B prologue (stages 0,1) ----
        load_Bchunk(Bs, cstart, 0, tid);
        asm volatile("cp.async.commit_group;" ::: "memory");
        load_Bchunk(Bs, cstart + 1, 1, tid);
        asm volatile("cp.async.commit_group;" ::: "memory");

        // ---- fill A: fp32 -> fp16 into swizzled smem ----
#pragma unroll 4
        for (int it = 0; it < 32; it++) {
            int idx = tid + it * 256;
            int r = idx >> 6, ch = idx & 63;
            const float4* src = reinterpret_cast<const float4*>(
                x + (size_t)(row0 + r) * Dn + ch * 8);
            float4 v0 = src[0], v1 = src[1];
            __half2 p0 = __floats2half2_rn(v0.x, v0.y);
            __half2 p1 = __floats2half2_rn(v0.z, v0.w);
            __half2 p2 = __floats2half2_rn(v1.x, v1.y);
            __half2 p3 = __floats2half2_rn(v1.z, v1.w);
            uint32_t dchunk = (uint32_t)((ch & ~7) | ((ch ^ r) & 7));
            uint32_t dst = As + r * 1024 + dchunk * 16;
            asm volatile("st.shared.v4.b32 [%0], {%1,%2,%3,%4};" ::
                "r"(dst),
                "r"(*reinterpret_cast<uint32_t*>(&p0)), "r"(*reinterpret_cast<uint32_t*>(&p1)),
                "r"(*reinterpret_cast<uint32_t*>(&p2)), "r"(*reinterpret_cast<uint32_t*>(&p3))
                : "memory");
        }

        for (int ct = 0; ct < nch; ct++) {
            const int cg = cstart + ct;
            const int vt = cg >> 3, kc = cg & 7, st = ct % 3;
            // one barrier per chunk: own groups for chunk ct landed (wait), then
            // the barrier both publishes chunk ct to all warps AND proves all
            // warps finished LDSM of ct-1 (whose stage (ct+2)%3 we reuse below).
            if (ct + 1 < nch) {
                asm volatile("cp.async.wait_group 1;" ::: "memory");
            } else {
                asm volatile("cp.async.wait_group 0;" ::: "memory");
            }
            __syncthreads();
            if (ct + 2 < nch) {
                load_Bchunk(Bs, cstart + ct + 2, (ct + 2) % 3, tid);
                asm volatile("cp.async.commit_group;" ::: "memory");
            }

            const uint32_t aCh = aBase + kc * 128;
            const uint32_t bSt = Bs + (uint32_t)st * 16384u + bn * 128;
#pragma unroll
            for (int ks = 0; ks < 4; ks++) {
                uint32_t afr[4][4];
#pragma unroll
                for (int mtl = 0; mtl < 4; mtl++) {
                    uint32_t ad = aCh + mtl * 16384 + (uint32_t)(((ks * 2 + alow) ^ arx)) * 16;
                    asm volatile("ldmatrix.sync.aligned.m8n8.x4.shared.b16 {%0,%1,%2,%3}, [%4];"
                        : "=r"(afr[mtl][0]), "=r"(afr[mtl][1]), "=r"(afr[mtl][2]), "=r"(afr[mtl][3])
                        : "r"(ad));
                }
                uint32_t bfr[2][4];
#pragma unroll
                for (int np = 0; np < 2; np++) {
                    uint32_t bd = bSt + np * 2048 + (uint32_t)(((ks * 2 + bko) ^ bnx)) * 16;
                    asm volatile("ldmatrix.sync.aligned.m8n8.x4.shared.b16 {%0,%1,%2,%3}, [%4];"
                        : "=r"(bfr[np][0]), "=r"(bfr[np][1]), "=r"(bfr[np][2]), "=r"(bfr[np][3])
                        : "r"(bd));
                }
#pragma unroll
                for (int mtl = 0; mtl < 4; mtl++)
#pragma unroll
                    for (int nt = 0; nt < 4; nt++) {
                        asm volatile("mma.sync.aligned.m16n8k16.row.col.f16.f16.f16.f16 "
                            "{%0,%1}, {%2,%3,%4,%5}, {%6,%7}, {%0,%1};"
                            : "+r"(acc[mtl][nt][0]), "+r"(acc[mtl][nt][1])
                            : "r"(afr[mtl][0]), "r"(afr[mtl][1]), "r"(afr[mtl][2]), "r"(afr[mtl][3]),
                              "r"(bfr[nt >> 1][(nt & 1) * 2]), "r"(bfr[nt >> 1][(nt & 1) * 2 + 1]));
                    }
            }

            if (kc == 7) {
                // ---- register-only epilogue for vtile vt ----
                float bcol[8];
#pragma unroll
                for (int nt = 0; nt < 4; nt++) {
                    bcol[nt * 2]     = sbias[vt * 128 + wn * 32 + nt * 8 + (lane & 3) * 2];
                    bcol[nt * 2 + 1] = sbias[vt * 128 + wn * 32 + nt * 8 + (lane & 3) * 2 + 1];
                }
                const int vbase = vt * 16 + wn * 4;
#pragma unroll
                for (int mtl = 0; mtl < 4; mtl++)
#pragma unroll
                    for (int h = 0; h < 2; h++) {
                        const int i = mtl * 2 + h;
#pragma unroll
                        for (int nt = 0; nt < 4; nt++) {
                            uint32_t pk = acc[mtl][nt][h];
                            float2 fv = __half22float2(*reinterpret_cast<__half2*>(&pk));
#pragma unroll
                            for (int lo = 0; lo < 2; lo++) {
                                float y = (lo ? fv.y : fv.x) + bcol[nt * 2 + lo];
                                sr[i] += y;
                                se[i] += exp2_fast(y * L2E);
                                if (tkey[i] == vbase + nt && tlo[i] == lo)
                                    g_tgt[grow[i]] = y;
                                if (vt == 0 && nt == 0 && lo == 0 && blankown)
                                    g_blank[grow[i]] = y;
                            }
                        }
                    }
#pragma unroll
                for (int a0 = 0; a0 < 4; a0++)
#pragma unroll
                    for (int b0 = 0; b0 < 4; b0++) { acc[a0][b0][0] = 0u; acc[a0][b0][1] = 0u; }
            }
        }

        // ---- fragment partial reduction + slotted write ----
#pragma unroll
        for (int i = 0; i < 8; i++) {
            se[i] += __shfl_xor_sync(0xffffffffu, se[i], 1);
            se[i] += __shfl_xor_sync(0xffffffffu, se[i], 2);
            sr[i] += __shfl_xor_sync(0xffffffffu, sr[i], 1);
            sr[i] += __shfl_xor_sync(0xffffffffu, sr[i], 2);
        }
        __syncthreads();
        if ((lane & 3) == 0) {
#pragma unroll
            for (int i = 0; i < 8; i++) {
                int mtl = i >> 1, h = i & 1;
                int lr = wm * 64 + mtl * 16 + (lane >> 2) + h * 8;
                lseb[wn * 128 + lr] = se[i];
                rawb[wn * 128 + lr] = sr[i];
            }
        }
        __syncthreads();
        if (tid < 128) {
            float E = (lseb[tid] + lseb[128 + tid]) + (lseb[256 + tid] + lseb[384 + tid]);
            float R = (rawb[tid] + rawb[128 + tid]) + (rawb[256 + tid] + rawb[384 + tid]);
            // segment -> slot: start / end / middle (3-way splits possible)
            if (vt0 == 0)             { g_pE0[row0 + tid] = E; g_pR0[row0 + tid] = R; }
            else if (vt0 + nvt == 32) { g_pE1[row0 + tid] = E; g_pR1[row0 + tid] = R; }
            else                      { g_pE2[row0 + tid] = E; g_pR2[row0 + tid] = R; }
        }
#pragma unroll
        for (int i = 0; i < 8; i++) { se[i] = 0.f; sr[i] = 0.f; }

        u += nvt;
    }
}

// ---------------------------------------------------------------------------
// Kernel 2: per-batch DP, branch-free, log2 domain; cp.async bulk staging
// ---------------------------------------------------------------------------
extern __shared__ float fsm[];

__global__ void __launch_bounds__(256) finalize_kernel(
    const int* __restrict__ targets,
    const int* __restrict__ src_lengths,
    const int* __restrict__ tgt_lengths,
    float* __restrict__ out)
{
    float* sbl = fsm;                  // BTUP
    float* sem = fsm + BTUP;           // BTUP
    float* sE0 = fsm + 2 * BTUP;       // BTU each
    float* sE1 = sE0 + BTU;
    float* sE2 = sE1 + BTU;
    float* sBL = sE2 + BTU;
    float* sTG = sBL + BTU;
    __shared__ float s_dp;
    const int b = blockIdx.x;
    const int tid = threadIdx.x;
    const int base = b * BTU;

    // ---- bulk cp.async staging of the 5 per-row arrays (fire-and-forget) ----
    {
        const uint32_t d0 = smem_u32(fsm) + 2u * BTUP * 4u;
        const float* gs0 = g_pE0 + base;
        const float* gs1 = g_pE1 + base;
        const float* gs2 = g_pE2 + base;
        const float* gs3 = g_blank + base;
        const float* gs4 = g_tgt + base;
        const int NOP = BTU / 4;       // 1056 16B ops per array
        for (int i = tid; i < NOP; i += 256) {
            cpa16(d0 + 0u * BTU * 4u + i * 16, gs0 + i * 4);
            cpa16(d0 + 1u * BTU * 4u + i * 16, gs1 + i * 4);
            cpa16(d0 + 2u * BTU * 4u + i * 16, gs2 + i * 4);
            cpa16(d0 + 3u * BTU * 4u + i * 16, gs3 + i * 4);
            cpa16(d0 + 4u * BTU * 4u + i * 16, gs4 + i * 4);
        }
        asm volatile("cp.async.commit_group;" ::: "memory");
        asm volatile("cp.async.wait_group 0;" ::: "memory");
        __syncthreads();
    }

    // ---- stage lattice in log2 domain, stride-34 padded (from smem) ----
    for (int i = tid; i < BTU; i += 256) {
        int t = i / U1n, uu = i - t * U1n;
        float E = (sE0[i] + sE1[i]) + sE2[i];
        float l2 = lg2a(E);
        int p = t * U1P + uu;
        sbl[p] = fmaf(sBL[i], L2E, -l2);
        sem[p] = fmaf(sTG[i], L2E, -l2);
    }
    __syncthreads();

    if (tid < 32) {
        const int lane = tid;
        const int S  = src_lengths[b];
        const int TG = tgt_lengths[b];

        // ---- alpha0 via Kogge-Stone exclusive scan of sem[0..30] ----
        float v = sem[(lane == 0) ? 0 : (lane - 1)];
        v = (lane == 0) ? 0.f : v;
#pragma unroll
        for (int o = 1; o < 32; o <<= 1) {
            float nv = __shfl_up_sync(0xffffffffu, v, o);
            v += (lane >= o) ? nv : 0.f;
        }
        float cur  = v;                                        // alpha[0][lane]
        float cur2 = __shfl_sync(0xffffffffu, cur, 31) + sem[31];  // alpha[0][32]

        float afin = 0.f, haveF = 0.f;
        const int nsteps = (S - 1) + 32;
        for (int s = 1; s <= nsteps; s++) {
            float left   = __shfl_up_sync(0xffffffffu, cur, 1);
            float prev31 = cur;                                // lane31: alpha[t2][31]
            int t  = s - lane;
            int tc = max(1, min(t, S - 1));
            float up   = cur + sbl[(tc - 1) * U1P + lane];
            float alt  = left + sem[tc * U1P + ((lane == 0) ? 0 : (lane - 1))];
            float cand = laddexp2(up, alt);
            cand = (lane == 0) ? up : cand;
            bool valid = (t >= 1) && (t <= S - 1);
            cur = valid ? cand : cur;
            bool hit = valid && (t == S - 1) && (lane == TG);
            afin  = hit ? cur : afin;
            haveF = hit ? 1.f : haveF;
            // column u=32: computed by all lanes; only lane31's value is real
            int t2  = s - 32;
            int t2c = max(1, min(t2, S - 1));
            float up2   = cur2 + sbl[(t2c - 1) * U1P + 32];
            float alt2  = prev31 + sem[t2c * U1P + 31];
            float cand2 = laddexp2(up2, alt2);
            bool valid2 = (t2 >= 1) && (t2 <= S - 1);
            cur2 = valid2 ? cand2 : cur2;
            bool hit2 = valid2 && (t2 == S - 1) && (TG == 32) && (lane == 31);
            afin  = hit2 ? cur2 : afin;
            haveF = hit2 ? 1.f : haveF;
        }
        float lossb = -(afin + sbl[(S - 1) * U1P + TG]) * LN2 * haveF;
#pragma unroll
        for (int o = 16; o > 0; o >>= 1)
            lossb += __shfl_xor_sync(0xffffffffu, lossb, o);
        if (lane == 0) s_dp = lossb;
    }
    __syncthreads();

    if (tid < 32) {
        const int uu = tid;
        const int S = src_lengths[b];
        const int tv = targets[b * (U1n - 1) + uu];
        const int lrow = (S - 1) * U1n + uu;
        const int row  = base + lrow;
        float E = (sE0[lrow] + sE1[lrow]) + sE2[lrow];
        float lse = lg2a(E) * LN2;
        float R = (g_pR0[row] + g_pR1[row]) + g_pR2[row];
        float nll = lse - sTG[lrow];
        float smooth = (float)Vn * lse - R;
        const float LS = 0.1f;
        const float eps = LS / (float)(Vn - 1);
        float m = (tv != 1) ? 1.f : 0.f;
        float term = ((1.f - LS - eps) * nll + eps * smooth) * m;
#pragma unroll
        for (int o = 16; o > 0; o >>= 1)
            term += __shfl_xor_sync(0xffffffffu, term, o);
        if (uu == 0) {
            g_part[b] = s_dp + term;
            __threadfence();
            unsigned t = atomicAdd(&g_done, 1u);
            if (t == (unsigned)(Bn - 1)) {
                __threadfence();
                float s = 0.f;
#pragma unroll
                for (int bb = 0; bb < Bn; bb++) s += g_part[bb];
                out[0] = s;
                g_done = 0u;           // reset for next graph replay
            }
        }
    }
}

// ---------------------------------------------------------------------------
extern "C" void kernel_launch(void* const* d_in, const int* in_sizes, int n_in,
                              void* d_out, int out_size)
{
    const float* x       = (const float*)d_in[0];
    const float* wgt     = (const float*)d_in[1];
    const float* bias    = (const float*)d_in[2];
    const int*   targets = (const int*)d_in[3];
    const int*   src     = (const int*)d_in[4];
    const int*   tgt     = (const int*)d_in[5];
    float* out = (float*)d_out;

    static bool attr_set = false;
    if (!attr_set) {
        cudaFuncSetAttribute(maingemm_kernel,
                             cudaFuncAttributeMaxDynamicSharedMemorySize, SM_TOT);
        cudaFuncSetAttribute(finalize_kernel,
                             cudaFuncAttributeMaxDynamicSharedMemorySize, FSM_BYTES);
        attr_set = true;
    }

    convW_kernel<<<(Vn * Dn / 8) / 256, 256>>>(wgt);
    schedule_kernel<<<1, 32>>>(src);
    maingemm_kernel<<<NCTA, 256, SM_TOT>>>(x, bias, targets);
    finalize_kernel<<<Bn, 256, FSM_BYTES>>>(targets, src, tgt, out);
}